// round 11
// baseline (speedup 1.0000x reference)
#include <cuda_runtime.h>
#include <cstdint>

// Problem constants
#define NB 4
#define NS 2048
#define ND 1024
#define NH 16
#define NDK 64
#define NM (NB*NS)   // 8192

// Persistent scratch (device globals: allocation-free, graph-safe)
__device__ float g_q[(size_t)NM * ND];    // [B,H,S,dk] (tf32-rounded)
__device__ float g_k[(size_t)NM * ND];    // [B,H,S,dk] (tf32-rounded)
__device__ float g_v[(size_t)NM * ND];    // [B,H,S,dk] (tf32-rounded)
__device__ float g_ctx[(size_t)NM * ND];  // [B,S,D]    (fp32)

// ---------------------------------------------------------------------------
// tf32 helpers
// ---------------------------------------------------------------------------
__device__ __forceinline__ float f2tf(float x) {
    uint32_t u;
    asm("cvt.rna.tf32.f32 %0, %1;" : "=r"(u) : "f"(x));
    return __uint_as_float(u);
}

__device__ __forceinline__ void mma_tf32(float d[4],
                                         uint32_t a0, uint32_t a1,
                                         uint32_t a2, uint32_t a3,
                                         uint32_t b0, uint32_t b1) {
    asm volatile(
        "mma.sync.aligned.m16n8k8.row.col.f32.tf32.tf32.f32 "
        "{%0,%1,%2,%3}, {%4,%5,%6,%7}, {%8,%9}, {%0,%1,%2,%3};"
        : "+f"(d[0]), "+f"(d[1]), "+f"(d[2]), "+f"(d[3])
        : "r"(a0), "r"(a1), "r"(a2), "r"(a3), "r"(b0), "r"(b1));
}

// ---------------------------------------------------------------------------
// GEMM: out[m,n] = sum_k X[m,k]*W[n,k] + bias[n]   (tf32 tensor cores)
// 128x128 tile, BK=16, 256 threads (8 warps: 4 m x 2 n), warp tile 32x64.
// Identical to the Round-4 passing version.
// ---------------------------------------------------------------------------
#define BKG 16

__global__ __launch_bounds__(256, 2)
void gemm_bias_k(const float* __restrict__ Xin, int x_sel,
                 const float* __restrict__ W, const float* __restrict__ bias,
                 float* __restrict__ Oout, int out_sel)
{
    const float* X = (x_sel == 0) ? Xin : g_ctx;
    float* out = (out_sel == 0) ? g_q : (out_sel == 1) ? g_k :
                 (out_sel == 2) ? g_v : Oout;

    __shared__ float As[2][128][20];
    __shared__ float Bs[2][128][20];

    const int tid  = threadIdx.x;
    const int lane = tid & 31;
    const int warp = tid >> 5;
    const int g    = lane >> 2;
    const int tg   = lane & 3;
    const int wm   = warp & 3;
    const int wn   = warp >> 2;
    const int row0 = blockIdx.y * 128;
    const int col0 = blockIdx.x * 128;

    float d[2][8][4];
    #pragma unroll
    for (int mi = 0; mi < 2; mi++)
        #pragma unroll
        for (int ni = 0; ni < 8; ni++)
            #pragma unroll
            for (int q = 0; q < 4; q++) d[mi][ni][q] = 0.f;

    #pragma unroll
    for (int w = 0; w < 2; w++) {
        int f  = tid + w * 256;
        int r  = f >> 2;
        int kb = (f & 3) << 2;
        float4 a = *(const float4*)(X + (size_t)(row0 + r) * ND + kb);
        float4 b = *(const float4*)(W + (size_t)(col0 + r) * ND + kb);
        *(float4*)&As[0][r][kb] = make_float4(f2tf(a.x), f2tf(a.y), f2tf(a.z), f2tf(a.w));
        *(float4*)&Bs[0][r][kb] = make_float4(f2tf(b.x), f2tf(b.y), f2tf(b.z), f2tf(b.w));
    }
    __syncthreads();

    #pragma unroll 2
    for (int k0 = 0; k0 < ND; k0 += BKG) {
        const int buf = (k0 >> 4) & 1;
        const int nxt = buf ^ 1;
        const bool more = (k0 + BKG) < ND;

        float4 pa[2], pb[2];
        if (more) {
            #pragma unroll
            for (int w = 0; w < 2; w++) {
                int f  = tid + w * 256;
                int r  = f >> 2;
                int kb = (f & 3) << 2;
                pa[w] = *(const float4*)(X + (size_t)(row0 + r) * ND + k0 + BKG + kb);
                pb[w] = *(const float4*)(W + (size_t)(col0 + r) * ND + k0 + BKG + kb);
            }
        }

        #pragma unroll
        for (int k8 = 0; k8 < BKG; k8 += 8) {
            uint32_t af[2][4], bf[8][2];
            #pragma unroll
            for (int mi = 0; mi < 2; mi++) {
                int rm = wm * 32 + mi * 16;
                af[mi][0] = __float_as_uint(As[buf][rm + g    ][k8 + tg]);
                af[mi][1] = __float_as_uint(As[buf][rm + g + 8][k8 + tg]);
                af[mi][2] = __float_as_uint(As[buf][rm + g    ][k8 + tg + 4]);
                af[mi][3] = __float_as_uint(As[buf][rm + g + 8][k8 + tg + 4]);
            }
            #pragma unroll
            for (int ni = 0; ni < 8; ni++) {
                int cn = wn * 64 + ni * 8;
                bf[ni][0] = __float_as_uint(Bs[buf][cn + g][k8 + tg]);
                bf[ni][1] = __float_as_uint(Bs[buf][cn + g][k8 + tg + 4]);
            }
            #pragma unroll
            for (int mi = 0; mi < 2; mi++)
                #pragma unroll
                for (int ni = 0; ni < 8; ni++)
                    mma_tf32(d[mi][ni], af[mi][0], af[mi][1], af[mi][2], af[mi][3],
                             bf[ni][0], bf[ni][1]);
        }

        if (more) {
            #pragma unroll
            for (int w = 0; w < 2; w++) {
                int f  = tid + w * 256;
                int r  = f >> 2;
                int kb = (f & 3) << 2;
                *(float4*)&As[nxt][r][kb] =
                    make_float4(f2tf(pa[w].x), f2tf(pa[w].y), f2tf(pa[w].z), f2tf(pa[w].w));
                *(float4*)&Bs[nxt][r][kb] =
                    make_float4(f2tf(pb[w].x), f2tf(pb[w].y), f2tf(pb[w].z), f2tf(pb[w].w));
            }
            __syncthreads();
        }
    }

    #pragma unroll
    for (int mi = 0; mi < 2; mi++) {
        #pragma unroll
        for (int ni = 0; ni < 8; ni++) {
            int c0 = col0 + wn * 64 + ni * 8 + tg * 2;
            float2 bb = *(const float2*)(bias + c0);
            int r0 = row0 + wm * 32 + mi * 16 + g;
            float2 v0 = make_float2(d[mi][ni][0] + bb.x, d[mi][ni][1] + bb.y);
            float2 v1 = make_float2(d[mi][ni][2] + bb.x, d[mi][ni][3] + bb.y);
            if (out_sel <= 2) {
                v0.x = f2tf(v0.x); v0.y = f2tf(v0.y);
                v1.x = f2tf(v1.x); v1.y = f2tf(v1.y);
                int hh = c0 >> 6, d0 = c0 & 63;
                int bt = r0 >> 11, s0 = r0 & (NS - 1);
                *(float2*)(out + (((size_t)(bt * NH + hh) * NS + s0) * NDK + d0)) = v0;
                int r1 = r0 + 8;
                int bt1 = r1 >> 11, s1 = r1 & (NS - 1);
                *(float2*)(out + (((size_t)(bt1 * NH + hh) * NS + s1) * NDK + d0)) = v1;
            } else {
                *(float2*)(out + (size_t)r0 * ND + c0) = v0;
                *(float2*)(out + (size_t)(r0 + 8) * ND + c0) = v1;
            }
        }
    }
}

// ---------------------------------------------------------------------------
// Flash attention (tf32 mma.sync), 256 threads / 8 warps.
// Register-prefetch double buffering (plain LDG, no async instructions):
// tile kt+1's K/V is loaded into registers right after the barrier and
// committed to smem at the next iteration's top, so the global-load latency
// is covered by GEMM1 + softmax + GEMM2 of tile kt.
// ---------------------------------------------------------------------------
#define KSOFF (128*68)
#define VSOFF (128*68 + 64*68)
#define ATTN_SMEM ((128*68 + 64*68 + 64*72) * 4)   // 70656 bytes

__global__ __launch_bounds__(256)
void attn_k(const float* __restrict__ relpos)
{
    extern __shared__ float sm[];
    float (*ps)[68] = (float(*)[68])sm;            // [128][68] P tile
    float (*ks)[68] = (float(*)[68])(sm + KSOFF);  // [64][68]  K tile
    float (*vs)[72] = (float(*)[72])(sm + VSOFF);  // [64][72]  V tile

    const int b    = blockIdx.x & (NB - 1);
    const int qt   = blockIdx.x >> 2;
    const int h    = blockIdx.y;
    const int tid  = threadIdx.x;
    const int lane = tid & 31;
    const int warp = tid >> 5;
    const int g    = lane >> 2;
    const int tg   = lane & 3;

    const float* qptr  = g_q + ((size_t)(b*NH + h) * NS + (size_t)qt*128) * NDK;
    const float* kbase = g_k + ((size_t)(b*NH + h) * NS) * NDK;
    const float* vbase = g_v + ((size_t)(b*NH + h) * NS) * NDK;
    const float* bias0 = relpos + ((size_t)h * NS + (size_t)qt*128 + warp*16) * NS;

    // Q fragments: rows warp*16+g and +8, all 64 k-cols (8 k8 steps)
    uint32_t qa[8][4];
    {
        const float* q0 = qptr + (size_t)(warp*16 + g) * NDK;
        const float* q1 = q0 + 8 * NDK;
        #pragma unroll
        for (int k8 = 0; k8 < 8; k8++) {
            qa[k8][0] = __float_as_uint(q0[k8*8 + tg]);
            qa[k8][1] = __float_as_uint(q1[k8*8 + tg]);
            qa[k8][2] = __float_as_uint(q0[k8*8 + tg + 4]);
            qa[k8][3] = __float_as_uint(q1[k8*8 + tg + 4]);
        }
    }

    // Prefetch registers: 4 float4 of K and 4 of V per thread (one 64x64 tile each)
    float4 pk[4], pv[4];
    // Prologue: tile 0 into registers
    #pragma unroll
    for (int w = 0; w < 4; w++) {
        int f  = tid + w*256;
        int r  = f >> 4;
        int dd = (f & 15) << 2;
        pk[w] = *(const float4*)(kbase + (size_t)r*NDK + dd);
        pv[w] = *(const float4*)(vbase + (size_t)r*NDK + dd);
    }

    float o[8][4];
    #pragma unroll
    for (int ni = 0; ni < 8; ni++)
        #pragma unroll
        for (int q = 0; q < 4; q++) o[ni][q] = 0.f;
    float m0 = -1e30f, m1 = -1e30f, l0 = 0.f, l1 = 0.f;

    for (int kt = 0; kt < NS/64; kt++) {
        // Commit prefetched tile kt to smem (smem free: bottom sync of prev iter)
        #pragma unroll
        for (int w = 0; w < 4; w++) {
            int f  = tid + w*256;
            int r  = f >> 4;
            int dd = (f & 15) << 2;
            *(float4*)&ks[r][dd] = pk[w];
            *(float4*)&vs[r][dd] = pv[w];
        }
        __syncthreads();

        // Issue tile kt+1 loads now; latency hidden under this tile's compute
        if (kt + 1 < NS/64) {
            const float* kg = kbase + (size_t)(kt+1)*64*NDK;
            const float* vg = vbase + (size_t)(kt+1)*64*NDK;
            #pragma unroll
            for (int w = 0; w < 4; w++) {
                int f  = tid + w*256;
                int r  = f >> 4;
                int dd = (f & 15) << 2;
                pk[w] = *(const float4*)(kg + (size_t)r*NDK + dd);
                pv[w] = *(const float4*)(vg + (size_t)r*NDK + dd);
            }
        }

        // Bias prefetch (overlaps with GEMM1)
        float2 br0[8], br1[8];
        {
            const float* bp0 = bias0 + (size_t)g * NS + kt*64 + tg*2;
            const float* bp1 = bp0 + 8 * NS;
            #pragma unroll
            for (int ni = 0; ni < 8; ni++) {
                br0[ni] = *(const float2*)(bp0 + ni*8);
                br1[ni] = *(const float2*)(bp1 + ni*8);
            }
        }

        // GEMM1: S(16x64 per warp) = Q . K^T
        float s[8][4];
        #pragma unroll
        for (int ni = 0; ni < 8; ni++)
            #pragma unroll
            for (int q = 0; q < 4; q++) s[ni][q] = 0.f;

        #pragma unroll
        for (int k8 = 0; k8 < 8; k8++) {
            uint32_t bf[8][2];
            #pragma unroll
            for (int ni = 0; ni < 8; ni++) {
                bf[ni][0] = __float_as_uint(ks[ni*8 + g][k8*8 + tg]);
                bf[ni][1] = __float_as_uint(ks[ni*8 + g][k8*8 + tg + 4]);
            }
            #pragma unroll
            for (int ni = 0; ni < 8; ni++)
                mma_tf32(s[ni], qa[k8][0], qa[k8][1], qa[k8][2], qa[k8][3],
                         bf[ni][0], bf[ni][1]);
        }

        // Scale + bias + online softmax
        float nm0 = m0, nm1 = m1;
        #pragma unroll
        for (int ni = 0; ni < 8; ni++) {
            s[ni][0] = fmaf(s[ni][0], 0.125f, br0[ni].x);
            s[ni][1] = fmaf(s[ni][1], 0.125f, br0[ni].y);
            s[ni][2] = fmaf(s[ni][2], 0.125f, br1[ni].x);
            s[ni][3] = fmaf(s[ni][3], 0.125f, br1[ni].y);
            nm0 = fmaxf(nm0, fmaxf(s[ni][0], s[ni][1]));
            nm1 = fmaxf(nm1, fmaxf(s[ni][2], s[ni][3]));
        }
        nm0 = fmaxf(nm0, __shfl_xor_sync(0xffffffffu, nm0, 1));
        nm0 = fmaxf(nm0, __shfl_xor_sync(0xffffffffu, nm0, 2));
        nm1 = fmaxf(nm1, __shfl_xor_sync(0xffffffffu, nm1, 1));
        nm1 = fmaxf(nm1, __shfl_xor_sync(0xffffffffu, nm1, 2));

        float corr0 = __expf(m0 - nm0);
        float corr1 = __expf(m1 - nm1);
        float rs0 = 0.f, rs1 = 0.f;
        const int pr = warp * 16 + g;
        #pragma unroll
        for (int ni = 0; ni < 8; ni++) {
            s[ni][0] = __expf(s[ni][0] - nm0);
            s[ni][1] = __expf(s[ni][1] - nm0);
            s[ni][2] = __expf(s[ni][2] - nm1);
            s[ni][3] = __expf(s[ni][3] - nm1);
            rs0 += s[ni][0] + s[ni][1];
            rs1 += s[ni][2] + s[ni][3];
            int c = ni*8 + tg*2;
            *(float2*)&ps[pr    ][c] = make_float2(f2tf(s[ni][0]), f2tf(s[ni][1]));
            *(float2*)&ps[pr + 8][c] = make_float2(f2tf(s[ni][2]), f2tf(s[ni][3]));
        }
        rs0 += __shfl_xor_sync(0xffffffffu, rs0, 1);
        rs0 += __shfl_xor_sync(0xffffffffu, rs0, 2);
        rs1 += __shfl_xor_sync(0xffffffffu, rs1, 1);
        rs1 += __shfl_xor_sync(0xffffffffu, rs1, 2);
        l0 = l0 * corr0 + rs0;
        l1 = l1 * corr1 + rs1;
        m0 = nm0; m1 = nm1;
        #pragma unroll
        for (int ni = 0; ni < 8; ni++) {
            o[ni][0] *= corr0; o[ni][1] *= corr0;
            o[ni][2] *= corr1; o[ni][3] *= corr1;
        }
        __syncwarp();   // order ps stores before intra-warp frag reloads

        // GEMM2: O += P . V
        #pragma unroll
        for (int k8 = 0; k8 < 8; k8++) {
            uint32_t af[4];
            af[0] = __float_as_uint(ps[warp*16 + g    ][k8*8 + tg]);
            af[1] = __float_as_uint(ps[warp*16 + g + 8][k8*8 + tg]);
            af[2] = __float_as_uint(ps[warp*16 + g    ][k8*8 + tg + 4]);
            af[3] = __float_as_uint(ps[warp*16 + g + 8][k8*8 + tg + 4]);
            uint32_t bf[8][2];
            #pragma unroll
            for (int ni = 0; ni < 8; ni++) {
                bf[ni][0] = __float_as_uint(vs[k8*8 + tg    ][ni*8 + g]);
                bf[ni][1] = __float_as_uint(vs[k8*8 + tg + 4][ni*8 + g]);
            }
            #pragma unroll
            for (int ni = 0; ni < 8; ni++)
                mma_tf32(o[ni], af[0], af[1], af[2], af[3], bf[ni][0], bf[ni][1]);
        }

        __syncthreads();   // all reads of ks/vs/ps done; safe to overwrite
    }

    // Normalize and write O to g_ctx [B,S,D]
    float inv0 = 1.f / l0, inv1 = 1.f / l1;
    int r0 = qt*128 + warp*16 + g;
    #pragma unroll
    for (int ni = 0; ni < 8; ni++) {
        int c = h*64 + ni*8 + tg*2;
        *(float2*)(g_ctx + (size_t)(b*NS + r0    ) * ND + c) =
            make_float2(o[ni][0]*inv0, o[ni][1]*inv0);
        *(float2*)(g_ctx + (size_t)(b*NS + r0 + 8) * ND + c) =
            make_float2(o[ni][2]*inv1, o[ni][3]*inv1);
    }
}

// ---------------------------------------------------------------------------
extern "C" void kernel_launch(void* const* d_in, const int* in_sizes, int n_in,
                              void* d_out, int out_size)
{
    const float* Q      = (const float*)d_in[0];
    const float* K      = (const float*)d_in[1];
    const float* V      = (const float*)d_in[2];
    const float* Wq     = (const float*)d_in[3];
    const float* bq     = (const float*)d_in[4];
    const float* Wk     = (const float*)d_in[5];
    const float* bk     = (const float*)d_in[6];
    const float* Wv     = (const float*)d_in[7];
    const float* bv     = (const float*)d_in[8];
    const float* Wo     = (const float*)d_in[9];
    const float* bo     = (const float*)d_in[10];
    const float* relpos = (const float*)d_in[11];
    float* out = (float*)d_out;

    cudaFuncSetAttribute(attn_k, cudaFuncAttributeMaxDynamicSharedMemorySize,
                         ATTN_SMEM);

    dim3 gproj(ND/128, NM/128);   // (8, 64)

    gemm_bias_k<<<gproj, 256>>>(Q, 0, Wq, bq, nullptr, 0);
    gemm_bias_k<<<gproj, 256>>>(K, 0, Wk, bk, nullptr, 1);
    gemm_bias_k<<<gproj, 256>>>(V, 0, Wv, bv, nullptr, 2);

    dim3 gattn(NB * (NS/128), NH);  // (64, 16), batch fastest for L2 bias reuse
    attn_k<<<gattn, 256, ATTN_SMEM>>>(relpos);

    gemm_bias_k<<<gproj, 256>>>(nullptr, 1, Wo, bo, out, 3);
}

// round 14
// speedup vs baseline: 1.7199x; 1.7199x over previous
#include <cuda_runtime.h>
#include <cuda_fp16.h>
#include <cstdint>

// Problem constants
#define NB 4
#define NS 2048
#define ND 1024
#define NH 16
#define NDK 64
#define NM (NB*NS)   // 8192

// Persistent scratch (device globals: allocation-free, graph-safe)
__device__ __half g_q[(size_t)NM * ND];   // [B,H,S,dk] fp16
__device__ __half g_k[(size_t)NM * ND];   // [B,H,S,dk] fp16
__device__ __half g_v[(size_t)NM * ND];   // [B,H,S,dk] fp16
__device__ float  g_ctx[(size_t)NM * ND]; // [B,S,D]    fp32

// ---------------------------------------------------------------------------
// helpers
// ---------------------------------------------------------------------------
__device__ __forceinline__ uint32_t f2h2(float lo, float hi) {
    __half2 h = __floats2half2_rn(lo, hi);
    return *reinterpret_cast<uint32_t*>(&h);
}

__device__ __forceinline__ void mma_f16(float d[4],
                                        uint32_t a0, uint32_t a1,
                                        uint32_t a2, uint32_t a3,
                                        uint32_t b0, uint32_t b1) {
    asm volatile(
        "mma.sync.aligned.m16n8k16.row.col.f32.f16.f16.f32 "
        "{%0,%1,%2,%3}, {%4,%5,%6,%7}, {%8,%9}, {%0,%1,%2,%3};"
        : "+f"(d[0]), "+f"(d[1]), "+f"(d[2]), "+f"(d[3])
        : "r"(a0), "r"(a1), "r"(a2), "r"(a3), "r"(b0), "r"(b1));
}

__device__ __forceinline__ void ldsm_x4_trans(uint32_t& r0, uint32_t& r1,
                                              uint32_t& r2, uint32_t& r3,
                                              uint32_t addr) {
    asm volatile(
        "ldmatrix.sync.aligned.m8n8.x4.trans.shared.b16 {%0,%1,%2,%3}, [%4];"
        : "=r"(r0), "=r"(r1), "=r"(r2), "=r"(r3) : "r"(addr));
}

__device__ __forceinline__ uint32_t smem_u32(const void* p) {
    return (uint32_t)__cvta_generic_to_shared(p);
}

// ---------------------------------------------------------------------------
// Projection GEMM (fp16 mma.sync m16n8k16): out[m,n] = X[m,:].W[n,:] + bias[n]
// 128x128 tile, BK=16 (one k16 step/stage), 256 threads (4m x 2n warps),
// register-prefetch double-buffered smem (fp16, 24-half pitch).
// out_sel 0/1/2 -> g_q/g_k/g_v fp16 [B,H,S,dk]; 3 -> fp32 [M,N].
// ---------------------------------------------------------------------------
__global__ __launch_bounds__(256, 2)
void gemm_h(const float* __restrict__ Xin, int x_sel,
            const float* __restrict__ W, const float* __restrict__ bias,
            float* __restrict__ Oout, int out_sel)
{
    const float* X = (x_sel == 0) ? Xin : g_ctx;
    __half* outh = (out_sel == 0) ? g_q : (out_sel == 1) ? g_k : g_v;

    __shared__ __half As[2][128][24];
    __shared__ __half Bs[2][128][24];

    const int tid  = threadIdx.x;
    const int lane = tid & 31;
    const int warp = tid >> 5;
    const int g    = lane >> 2;
    const int tg   = lane & 3;
    const int wm   = warp & 3;
    const int wn   = warp >> 2;
    const int row0 = blockIdx.y * 128;
    const int col0 = blockIdx.x * 128;

    float d[2][8][4];
    #pragma unroll
    for (int mi = 0; mi < 2; mi++)
        #pragma unroll
        for (int ni = 0; ni < 8; ni++)
            #pragma unroll
            for (int q = 0; q < 4; q++) d[mi][ni][q] = 0.f;

    // Prologue: stage 0
    #pragma unroll
    for (int w = 0; w < 2; w++) {
        int f  = tid + w * 256;
        int r  = f >> 2;
        int kb = (f & 3) << 2;
        float4 a = *(const float4*)(X + (size_t)(row0 + r) * ND + kb);
        float4 b = *(const float4*)(W + (size_t)(col0 + r) * ND + kb);
        *(uint2*)&As[0][r][kb] = make_uint2(f2h2(a.x, a.y), f2h2(a.z, a.w));
        *(uint2*)&Bs[0][r][kb] = make_uint2(f2h2(b.x, b.y), f2h2(b.z, b.w));
    }
    __syncthreads();

    #pragma unroll 2
    for (int k0 = 0; k0 < ND; k0 += 16) {
        const int buf = (k0 >> 4) & 1;
        const int nxt = buf ^ 1;
        const bool more = (k0 + 16) < ND;

        float4 pa[2], pb[2];
        if (more) {
            #pragma unroll
            for (int w = 0; w < 2; w++) {
                int f  = tid + w * 256;
                int r  = f >> 2;
                int kb = (f & 3) << 2;
                pa[w] = *(const float4*)(X + (size_t)(row0 + r) * ND + k0 + 16 + kb);
                pb[w] = *(const float4*)(W + (size_t)(col0 + r) * ND + k0 + 16 + kb);
            }
        }

        // One k16 step: 16 MMAs
        {
            uint32_t af[2][4], bf[8][2];
            #pragma unroll
            for (int mi = 0; mi < 2; mi++) {
                int rm = wm * 32 + mi * 16;
                af[mi][0] = *(const uint32_t*)&As[buf][rm + g    ][2*tg];
                af[mi][1] = *(const uint32_t*)&As[buf][rm + g + 8][2*tg];
                af[mi][2] = *(const uint32_t*)&As[buf][rm + g    ][2*tg + 8];
                af[mi][3] = *(const uint32_t*)&As[buf][rm + g + 8][2*tg + 8];
            }
            #pragma unroll
            for (int ni = 0; ni < 8; ni++) {
                int cn = wn * 64 + ni * 8;
                bf[ni][0] = *(const uint32_t*)&Bs[buf][cn + g][2*tg];
                bf[ni][1] = *(const uint32_t*)&Bs[buf][cn + g][2*tg + 8];
            }
            #pragma unroll
            for (int mi = 0; mi < 2; mi++)
                #pragma unroll
                for (int ni = 0; ni < 8; ni++)
                    mma_f16(d[mi][ni], af[mi][0], af[mi][1], af[mi][2], af[mi][3],
                            bf[ni][0], bf[ni][1]);
        }

        if (more) {
            #pragma unroll
            for (int w = 0; w < 2; w++) {
                int f  = tid + w * 256;
                int r  = f >> 2;
                int kb = (f & 3) << 2;
                *(uint2*)&As[nxt][r][kb] = make_uint2(f2h2(pa[w].x, pa[w].y),
                                                      f2h2(pa[w].z, pa[w].w));
                *(uint2*)&Bs[nxt][r][kb] = make_uint2(f2h2(pb[w].x, pb[w].y),
                                                      f2h2(pb[w].z, pb[w].w));
            }
            __syncthreads();
        }
    }

    // Epilogue: bias + write
    #pragma unroll
    for (int mi = 0; mi < 2; mi++) {
        #pragma unroll
        for (int ni = 0; ni < 8; ni++) {
            int c0 = col0 + wn * 64 + ni * 8 + tg * 2;
            float2 bb = *(const float2*)(bias + c0);
            int r0 = row0 + wm * 32 + mi * 16 + g;
            float2 v0 = make_float2(d[mi][ni][0] + bb.x, d[mi][ni][1] + bb.y);
            float2 v1 = make_float2(d[mi][ni][2] + bb.x, d[mi][ni][3] + bb.y);
            if (out_sel <= 2) {
                int hh = c0 >> 6, d0 = c0 & 63;
                int bt = r0 >> 11, s0 = r0 & (NS - 1);
                *(uint32_t*)(outh + (((size_t)(bt*NH + hh) * NS + s0) * NDK + d0)) =
                    f2h2(v0.x, v0.y);
                int r1 = r0 + 8;
                int bt1 = r1 >> 11, s1 = r1 & (NS - 1);
                *(uint32_t*)(outh + (((size_t)(bt1*NH + hh) * NS + s1) * NDK + d0)) =
                    f2h2(v1.x, v1.y);
            } else {
                *(float2*)(Oout + (size_t)r0 * ND + c0) = v0;
                *(float2*)(Oout + (size_t)(r0 + 8) * ND + c0) = v1;
            }
        }
    }
}

// ---------------------------------------------------------------------------
// Flash attention (fp16 mma.sync m16n8k16), 256 threads / 8 warps (R4 shape).
// K frags: contiguous b32 LDS. V frags: ldmatrix.x4.trans (no transposed
// store needed). P stored as half2. All accumulation fp32.
// Smem (halves, pitch 72): ps[128][72], ks[64][72], vs[64][72] = 36864 B.
// ---------------------------------------------------------------------------
#define PS_H  (128*72)
#define KS_H  (PS_H + 64*72)
#define ATTN_SMEM ((128*72 + 64*72 + 64*72) * 2)   // 36864 bytes

__global__ __launch_bounds__(256)
void attn_k(const float* __restrict__ relpos)
{
    extern __shared__ __half smh[];
    __half (*ps16)[72] = (__half(*)[72])smh;
    __half (*ks16)[72] = (__half(*)[72])(smh + PS_H);
    __half (*vs16)[72] = (__half(*)[72])(smh + KS_H);

    const int b    = blockIdx.x & (NB - 1);
    const int qt   = blockIdx.x >> 2;
    const int h    = blockIdx.y;
    const int tid  = threadIdx.x;
    const int lane = tid & 31;
    const int warp = tid >> 5;
    const int g    = lane >> 2;
    const int tg   = lane & 3;

    const __half* qptr  = g_q + ((size_t)(b*NH + h) * NS + (size_t)qt*128) * NDK;
    const __half* kb16  = g_k + ((size_t)(b*NH + h) * NS) * NDK;
    const __half* vb16  = g_v + ((size_t)(b*NH + h) * NS) * NDK;
    const float*  bias0 = relpos + ((size_t)h * NS + (size_t)qt*128 + warp*16) * NS;

    // Q fragments: rows warp*16+g, +8; 4 k16 steps
    uint32_t qa[4][4];
    {
        const __half* q0 = qptr + (size_t)(warp*16 + g) * NDK;
        const __half* q1 = q0 + 8 * NDK;
        #pragma unroll
        for (int k16 = 0; k16 < 4; k16++) {
            qa[k16][0] = *(const uint32_t*)&q0[k16*16 + 2*tg];
            qa[k16][1] = *(const uint32_t*)&q1[k16*16 + 2*tg];
            qa[k16][2] = *(const uint32_t*)&q0[k16*16 + 2*tg + 8];
            qa[k16][3] = *(const uint32_t*)&q1[k16*16 + 2*tg + 8];
        }
    }

    // ldmatrix.x4.trans lane-invariant address part for V
    const int mm = lane >> 3, rr = lane & 7;
    const uint32_t ldsm_inv = smem_u32(&vs16[0][0])
                            + (uint32_t)(((mm & 1)*8 + rr) * 144 + (mm >> 1) * 16);

    float o[8][4];
    #pragma unroll
    for (int ni = 0; ni < 8; ni++)
        #pragma unroll
        for (int q = 0; q < 4; q++) o[ni][q] = 0.f;
    float m0 = -1e30f, m1 = -1e30f, l0 = 0.f, l1 = 0.f;

    for (int kt = 0; kt < NS/64; kt++) {
        __syncthreads();
        // Commit K/V tile (fp16 global -> fp16 smem, uint4 = 8 halves)
        #pragma unroll
        for (int w = 0; w < 2; w++) {
            int f  = tid + w*256;          // 0..511
            int r  = f >> 3;               // 0..63
            int c8 = (f & 7) << 3;         // 0..56
            *(uint4*)&ks16[r][c8] =
                *(const uint4*)(kb16 + (size_t)(kt*64 + r)*NDK + c8);
            *(uint4*)&vs16[r][c8] =
                *(const uint4*)(vb16 + (size_t)(kt*64 + r)*NDK + c8);
        }
        __syncthreads();

        // Bias prefetch (overlaps with GEMM1)
        float2 br0[8], br1[8];
        {
            const float* bp0 = bias0 + (size_t)g * NS + kt*64 + tg*2;
            const float* bp1 = bp0 + 8 * NS;
            #pragma unroll
            for (int ni = 0; ni < 8; ni++) {
                br0[ni] = *(const float2*)(bp0 + ni*8);
                br1[ni] = *(const float2*)(bp1 + ni*8);
            }
        }

        // GEMM1: S(16x64/warp) = Q.K^T  (32 MMAs)
        float s[8][4];
        #pragma unroll
        for (int ni = 0; ni < 8; ni++)
            #pragma unroll
            for (int q = 0; q < 4; q++) s[ni][q] = 0.f;

        #pragma unroll
        for (int k16 = 0; k16 < 4; k16++) {
            uint32_t bf[8][2];
            #pragma unroll
            for (int ni = 0; ni < 8; ni++) {
                bf[ni][0] = *(const uint32_t*)&ks16[ni*8 + g][k16*16 + 2*tg];
                bf[ni][1] = *(const uint32_t*)&ks16[ni*8 + g][k16*16 + 2*tg + 8];
            }
            #pragma unroll
            for (int ni = 0; ni < 8; ni++)
                mma_f16(s[ni], qa[k16][0], qa[k16][1], qa[k16][2], qa[k16][3],
                        bf[ni][0], bf[ni][1]);
        }

        // Scale + bias + online softmax (rows warp*16+g, +8)
        float nm0 = m0, nm1 = m1;
        #pragma unroll
        for (int ni = 0; ni < 8; ni++) {
            s[ni][0] = fmaf(s[ni][0], 0.125f, br0[ni].x);
            s[ni][1] = fmaf(s[ni][1], 0.125f, br0[ni].y);
            s[ni][2] = fmaf(s[ni][2], 0.125f, br1[ni].x);
            s[ni][3] = fmaf(s[ni][3], 0.125f, br1[ni].y);
            nm0 = fmaxf(nm0, fmaxf(s[ni][0], s[ni][1]));
            nm1 = fmaxf(nm1, fmaxf(s[ni][2], s[ni][3]));
        }
        nm0 = fmaxf(nm0, __shfl_xor_sync(0xffffffffu, nm0, 1));
        nm0 = fmaxf(nm0, __shfl_xor_sync(0xffffffffu, nm0, 2));
        nm1 = fmaxf(nm1, __shfl_xor_sync(0xffffffffu, nm1, 1));
        nm1 = fmaxf(nm1, __shfl_xor_sync(0xffffffffu, nm1, 2));

        float corr0 = __expf(m0 - nm0);
        float corr1 = __expf(m1 - nm1);
        float rs0 = 0.f, rs1 = 0.f;
        const int pr = warp * 16 + g;
        #pragma unroll
        for (int ni = 0; ni < 8; ni++) {
            s[ni][0] = __expf(s[ni][0] - nm0);
            s[ni][1] = __expf(s[ni][1] - nm0);
            s[ni][2] = __expf(s[ni][2] - nm1);
            s[ni][3] = __expf(s[ni][3] - nm1);
            rs0 += s[ni][0] + s[ni][1];
            rs1 += s[ni][2] + s[ni][3];
            int c = ni*8 + tg*2;
            *(uint32_t*)&ps16[pr    ][c] = f2h2(s[ni][0], s[ni][1]);
            *(uint32_t*)&ps16[pr + 8][c] = f2h2(s[ni][2], s[ni][3]);
        }
        rs0 += __shfl_xor_sync(0xffffffffu, rs0, 1);
        rs0 += __shfl_xor_sync(0xffffffffu, rs0, 2);
        rs1 += __shfl_xor_sync(0xffffffffu, rs1, 1);
        rs1 += __shfl_xor_sync(0xffffffffu, rs1, 2);
        l0 = l0 * corr0 + rs0;
        l1 = l1 * corr1 + rs1;
        m0 = nm0; m1 = nm1;
        #pragma unroll
        for (int ni = 0; ni < 8; ni++) {
            o[ni][0] *= corr0; o[ni][1] *= corr0;
            o[ni][2] *= corr1; o[ni][3] *= corr1;
        }
        __syncwarp();   // order ps stores before intra-warp frag reloads

        // GEMM2: O += P.V   (A from own P rows; B via ldmatrix.x4.trans)
        #pragma unroll
        for (int k16 = 0; k16 < 4; k16++) {
            uint32_t af[4];
            af[0] = *(const uint32_t*)&ps16[pr    ][k16*16 + 2*tg];
            af[1] = *(const uint32_t*)&ps16[pr + 8][k16*16 + 2*tg];
            af[2] = *(const uint32_t*)&ps16[pr    ][k16*16 + 2*tg + 8];
            af[3] = *(const uint32_t*)&ps16[pr + 8][k16*16 + 2*tg + 8];
            #pragma unroll
            for (int nb = 0; nb < 4; nb++) {
                uint32_t b0, b1, b2, b3;
                ldsm_x4_trans(b0, b1, b2, b3,
                              ldsm_inv + (uint32_t)(k16*2304 + nb*32));
                mma_f16(o[nb*2    ], af[0], af[1], af[2], af[3], b0, b1);
                mma_f16(o[nb*2 + 1], af[0], af[1], af[2], af[3], b2, b3);
            }
        }
        // top-of-loop __syncthreads protects ks/vs/ps for the next tile
    }

    // Normalize and write O to g_ctx [B,S,D]
    float inv0 = 1.f / l0, inv1 = 1.f / l1;
    int r0 = qt*128 + warp*16 + g;
    #pragma unroll
    for (int ni = 0; ni < 8; ni++) {
        int c = h*64 + ni*8 + tg*2;
        *(float2*)(g_ctx + (size_t)(b*NS + r0    ) * ND + c) =
            make_float2(o[ni][0]*inv0, o[ni][1]*inv0);
        *(float2*)(g_ctx + (size_t)(b*NS + r0 + 8) * ND + c) =
            make_float2(o[ni][2]*inv1, o[ni][3]*inv1);
    }
}

// ---------------------------------------------------------------------------
extern "C" void kernel_launch(void* const* d_in, const int* in_sizes, int n_in,
                              void* d_out, int out_size)
{
    const float* Q      = (const float*)d_in[0];
    const float* K      = (const float*)d_in[1];
    const float* V      = (const float*)d_in[2];
    const float* Wq     = (const float*)d_in[3];
    const float* bq     = (const float*)d_in[4];
    const float* Wk     = (const float*)d_in[5];
    const float* bk     = (const float*)d_in[6];
    const float* Wv     = (const float*)d_in[7];
    const float* bv     = (const float*)d_in[8];
    const float* Wo     = (const float*)d_in[9];
    const float* bo     = (const float*)d_in[10];
    const float* relpos = (const float*)d_in[11];
    float* out = (float*)d_out;

    cudaFuncSetAttribute(attn_k, cudaFuncAttributeMaxDynamicSharedMemorySize,
                         ATTN_SMEM);

    dim3 gproj(ND/128, NM/128);   // (8, 64)

    gemm_h<<<gproj, 256>>>(Q, 0, Wq, bq, nullptr, 0);
    gemm_h<<<gproj, 256>>>(K, 0, Wk, bk, nullptr, 1);
    gemm_h<<<gproj, 256>>>(V, 0, Wv, bv, nullptr, 2);

    dim3 gattn(NB * (NS/128), NH);  // (64, 16), batch fastest for L2 bias reuse
    attn_k<<<gattn, 256, ATTN_SMEM>>>(relpos);

    gemm_h<<<gproj, 256>>>(nullptr, 1, Wo, bo, out, 3);
}

// round 15
// speedup vs baseline: 1.9030x; 1.1065x over previous
#include <cuda_runtime.h>
#include <cuda_fp16.h>
#include <cstdint>

// Problem constants
#define NB 4
#define NS 2048
#define ND 1024
#define NH 16
#define NDK 64
#define NM (NB*NS)   // 8192

// Persistent scratch (device globals: allocation-free, graph-safe)
__device__ __half g_q[(size_t)NM * ND];   // [B,H,S,dk] fp16
__device__ __half g_k[(size_t)NM * ND];   // [B,H,S,dk] fp16
__device__ __half g_v[(size_t)NM * ND];   // [B,H,S,dk] fp16
__device__ float  g_ctx[(size_t)NM * ND]; // [B,S,D]    fp32

// ---------------------------------------------------------------------------
// helpers
// ---------------------------------------------------------------------------
__device__ __forceinline__ uint32_t f2h2(float lo, float hi) {
    __half2 h = __floats2half2_rn(lo, hi);
    return *reinterpret_cast<uint32_t*>(&h);
}

__device__ __forceinline__ void mma_f16(float d[4],
                                        uint32_t a0, uint32_t a1,
                                        uint32_t a2, uint32_t a3,
                                        uint32_t b0, uint32_t b1) {
    asm volatile(
        "mma.sync.aligned.m16n8k16.row.col.f32.f16.f16.f32 "
        "{%0,%1,%2,%3}, {%4,%5,%6,%7}, {%8,%9}, {%0,%1,%2,%3};"
        : "+f"(d[0]), "+f"(d[1]), "+f"(d[2]), "+f"(d[3])
        : "r"(a0), "r"(a1), "r"(a2), "r"(a3), "r"(b0), "r"(b1));
}

__device__ __forceinline__ void ldsm_x4(uint32_t& r0, uint32_t& r1,
                                        uint32_t& r2, uint32_t& r3,
                                        uint32_t addr) {
    asm volatile(
        "ldmatrix.sync.aligned.m8n8.x4.shared.b16 {%0,%1,%2,%3}, [%4];"
        : "=r"(r0), "=r"(r1), "=r"(r2), "=r"(r3) : "r"(addr));
}

__device__ __forceinline__ void ldsm_x4_trans(uint32_t& r0, uint32_t& r1,
                                              uint32_t& r2, uint32_t& r3,
                                              uint32_t addr) {
    asm volatile(
        "ldmatrix.sync.aligned.m8n8.x4.trans.shared.b16 {%0,%1,%2,%3}, [%4];"
        : "=r"(r0), "=r"(r1), "=r"(r2), "=r"(r3) : "r"(addr));
}

__device__ __forceinline__ uint32_t smem_u32(const void* p) {
    return (uint32_t)__cvta_generic_to_shared(p);
}

// ---------------------------------------------------------------------------
// Projection GEMM (fp16 m16n8k16, ldmatrix fragments).
// mode 0: fused QKV (blockIdx.z selects input/weight/bias -> g_q/g_k/g_v)
// mode 1: output projection (X=g_ctx, W=Wq param, bias=bq param -> Oout fp32)
// 128x128 tile, BK=16, 256 threads (4m x 2n warps), reg-prefetch double buffer.
// ---------------------------------------------------------------------------
__global__ __launch_bounds__(256, 2)
void gemm_h(const float* __restrict__ Qi, const float* __restrict__ Ki,
            const float* __restrict__ Vi,
            const float* __restrict__ Wq, const float* __restrict__ Wk,
            const float* __restrict__ Wv,
            const float* __restrict__ bq, const float* __restrict__ bk,
            const float* __restrict__ bv,
            float* __restrict__ Oout, int mode)
{
    const int sel = (mode == 0) ? (int)blockIdx.z : 3;
    const float* X    = (sel==0) ? Qi : (sel==1) ? Ki : (sel==2) ? Vi : g_ctx;
    const float* W    = (sel==1) ? Wk : (sel==2) ? Wv : Wq;
    const float* bias = (sel==1) ? bk : (sel==2) ? bv : bq;
    __half* outh = (sel==0) ? g_q : (sel==1) ? g_k : g_v;

    __shared__ __half As[2][128][24];
    __shared__ __half Bs[2][128][24];

    const int tid  = threadIdx.x;
    const int lane = tid & 31;
    const int warp = tid >> 5;
    const int g    = lane >> 2;
    const int tg   = lane & 3;
    const int mm   = lane >> 3;
    const int rr   = lane & 7;
    const int wm   = warp & 3;
    const int wn   = warp >> 2;
    const int row0 = blockIdx.y * 128;
    const int col0 = blockIdx.x * 128;

    float d[2][8][4];
    #pragma unroll
    for (int mi = 0; mi < 2; mi++)
        #pragma unroll
        for (int ni = 0; ni < 8; ni++)
            #pragma unroll
            for (int q = 0; q < 4; q++) d[mi][ni][q] = 0.f;

    // Prologue: stage 0
    #pragma unroll
    for (int w = 0; w < 2; w++) {
        int f  = tid + w * 256;
        int r  = f >> 2;
        int kb = (f & 3) << 2;
        float4 a = *(const float4*)(X + (size_t)(row0 + r) * ND + kb);
        float4 b = *(const float4*)(W + (size_t)(col0 + r) * ND + kb);
        *(uint2*)&As[0][r][kb] = make_uint2(f2h2(a.x, a.y), f2h2(a.z, a.w));
        *(uint2*)&Bs[0][r][kb] = make_uint2(f2h2(b.x, b.y), f2h2(b.z, b.w));
    }
    __syncthreads();

    #pragma unroll 2
    for (int k0 = 0; k0 < ND; k0 += 16) {
        const int buf = (k0 >> 4) & 1;
        const int nxt = buf ^ 1;
        const bool more = (k0 + 16) < ND;

        float4 pa[2], pb[2];
        if (more) {
            #pragma unroll
            for (int w = 0; w < 2; w++) {
                int f  = tid + w * 256;
                int r  = f >> 2;
                int kb = (f & 3) << 2;
                pa[w] = *(const float4*)(X + (size_t)(row0 + r) * ND + k0 + 16 + kb);
                pb[w] = *(const float4*)(W + (size_t)(col0 + r) * ND + k0 + 16 + kb);
            }
        }

        // One k16 step: 6 ldmatrix + 16 MMAs
        {
            uint32_t af[2][4], bf[8][2];
            #pragma unroll
            for (int mi = 0; mi < 2; mi++) {
                uint32_t addr = smem_u32(
                    &As[buf][wm*32 + mi*16 + (mm&1)*8 + rr][(mm>>1)*8]);
                ldsm_x4(af[mi][0], af[mi][1], af[mi][2], af[mi][3], addr);
            }
            #pragma unroll
            for (int nip = 0; nip < 4; nip++) {
                uint32_t addr = smem_u32(
                    &Bs[buf][wn*64 + nip*16 + (mm&1)*8 + rr][(mm>>1)*8]);
                uint32_t r0, r1, r2, r3;
                ldsm_x4(r0, r1, r2, r3, addr);
                bf[2*nip][0] = r0; bf[2*nip+1][0] = r1;
                bf[2*nip][1] = r2; bf[2*nip+1][1] = r3;
            }
            #pragma unroll
            for (int mi = 0; mi < 2; mi++)
                #pragma unroll
                for (int ni = 0; ni < 8; ni++)
                    mma_f16(d[mi][ni], af[mi][0], af[mi][1], af[mi][2], af[mi][3],
                            bf[ni][0], bf[ni][1]);
        }

        if (more) {
            #pragma unroll
            for (int w = 0; w < 2; w++) {
                int f  = tid + w * 256;
                int r  = f >> 2;
                int kb = (f & 3) << 2;
                *(uint2*)&As[nxt][r][kb] = make_uint2(f2h2(pa[w].x, pa[w].y),
                                                      f2h2(pa[w].z, pa[w].w));
                *(uint2*)&Bs[nxt][r][kb] = make_uint2(f2h2(pb[w].x, pb[w].y),
                                                      f2h2(pb[w].z, pb[w].w));
            }
            __syncthreads();
        }
    }

    // Epilogue: bias + write
    #pragma unroll
    for (int mi = 0; mi < 2; mi++) {
        #pragma unroll
        for (int ni = 0; ni < 8; ni++) {
            int c0 = col0 + wn * 64 + ni * 8 + tg * 2;
            float2 bb = *(const float2*)(bias + c0);
            int r0 = row0 + wm * 32 + mi * 16 + g;
            float2 v0 = make_float2(d[mi][ni][0] + bb.x, d[mi][ni][1] + bb.y);
            float2 v1 = make_float2(d[mi][ni][2] + bb.x, d[mi][ni][3] + bb.y);
            if (sel <= 2) {
                int hh = c0 >> 6, d0 = c0 & 63;
                int bt = r0 >> 11, s0 = r0 & (NS - 1);
                *(uint32_t*)(outh + (((size_t)(bt*NH + hh) * NS + s0) * NDK + d0)) =
                    f2h2(v0.x, v0.y);
                int r1 = r0 + 8;
                int bt1 = r1 >> 11, s1 = r1 & (NS - 1);
                *(uint32_t*)(outh + (((size_t)(bt1*NH + hh) * NS + s1) * NDK + d0)) =
                    f2h2(v1.x, v1.y);
            } else {
                *(float2*)(Oout + (size_t)r0 * ND + c0) = v0;
                *(float2*)(Oout + (size_t)(r0 + 8) * ND + c0) = v1;
            }
        }
    }
}

// ---------------------------------------------------------------------------
// Flash attention (fp16 m16n8k16), 256 threads / 8 warps.
// S-accumulator layout == A-fragment layout => P stays entirely in registers
// (no smem round-trip). K frags via ldmatrix.x4; V via ldmatrix.x4.trans.
// Static smem: ks[64][72] + vs[64][72] = 18432 B.
// ---------------------------------------------------------------------------
__global__ __launch_bounds__(256)
void attn_k(const float* __restrict__ relpos)
{
    __shared__ __half ks16[64][72];
    __shared__ __half vs16[64][72];

    const int b    = blockIdx.x & (NB - 1);
    const int qt   = blockIdx.x >> 2;
    const int h    = blockIdx.y;
    const int tid  = threadIdx.x;
    const int lane = tid & 31;
    const int warp = tid >> 5;
    const int g    = lane >> 2;
    const int tg   = lane & 3;
    const int mm   = lane >> 3;
    const int rr   = lane & 7;

    const __half* qptr  = g_q + ((size_t)(b*NH + h) * NS + (size_t)qt*128) * NDK;
    const __half* kb16  = g_k + ((size_t)(b*NH + h) * NS) * NDK;
    const __half* vb16  = g_v + ((size_t)(b*NH + h) * NS) * NDK;
    const float*  bias0 = relpos + ((size_t)h * NS + (size_t)qt*128 + warp*16) * NS;

    // Q fragments: rows warp*16+g, +8; 4 k16 steps
    uint32_t qa[4][4];
    {
        const __half* q0 = qptr + (size_t)(warp*16 + g) * NDK;
        const __half* q1 = q0 + 8 * NDK;
        #pragma unroll
        for (int k16 = 0; k16 < 4; k16++) {
            qa[k16][0] = *(const uint32_t*)&q0[k16*16 + 2*tg];
            qa[k16][1] = *(const uint32_t*)&q1[k16*16 + 2*tg];
            qa[k16][2] = *(const uint32_t*)&q0[k16*16 + 2*tg + 8];
            qa[k16][3] = *(const uint32_t*)&q1[k16*16 + 2*tg + 8];
        }
    }

    // ldmatrix lane-invariant address parts (same lane->matrix convention as
    // the R14-proven .trans usage: lanes[8m..8m+7] -> matrix m rows)
    const uint32_t kf_inv = smem_u32(&ks16[0][0])
                          + (uint32_t)(((mm & 1)*8 + rr) * 144 + (mm >> 1) * 16);
    const uint32_t vf_inv = smem_u32(&vs16[0][0])
                          + (uint32_t)(((mm & 1)*8 + rr) * 144 + (mm >> 1) * 16);

    float o[8][4];
    #pragma unroll
    for (int ni = 0; ni < 8; ni++)
        #pragma unroll
        for (int q = 0; q < 4; q++) o[ni][q] = 0.f;
    float m0 = -1e30f, m1 = -1e30f, l0 = 0.f, l1 = 0.f;

    for (int kt = 0; kt < NS/64; kt++) {
        __syncthreads();
        // Commit K/V tile (fp16 global -> fp16 smem, uint4 = 8 halves)
        #pragma unroll
        for (int w = 0; w < 2; w++) {
            int f  = tid + w*256;          // 0..511
            int r  = f >> 3;               // 0..63
            int c8 = (f & 7) << 3;         // 0..56
            *(uint4*)&ks16[r][c8] =
                *(const uint4*)(kb16 + (size_t)(kt*64 + r)*NDK + c8);
            *(uint4*)&vs16[r][c8] =
                *(const uint4*)(vb16 + (size_t)(kt*64 + r)*NDK + c8);
        }
        __syncthreads();

        // Bias prefetch (overlaps with GEMM1)
        float2 br0[8], br1[8];
        {
            const float* bp0 = bias0 + (size_t)g * NS + kt*64 + tg*2;
            const float* bp1 = bp0 + 8 * NS;
            #pragma unroll
            for (int ni = 0; ni < 8; ni++) {
                br0[ni] = *(const float2*)(bp0 + ni*8);
                br1[ni] = *(const float2*)(bp1 + ni*8);
            }
        }

        // GEMM1: S(16x64/warp) = Q.K^T  (16 ldmatrix + 32 MMAs)
        float s[8][4];
        #pragma unroll
        for (int ni = 0; ni < 8; ni++)
            #pragma unroll
            for (int q = 0; q < 4; q++) s[ni][q] = 0.f;

        #pragma unroll
        for (int k16 = 0; k16 < 4; k16++) {
            #pragma unroll
            for (int nip = 0; nip < 4; nip++) {
                uint32_t r0, r1, r2, r3;
                ldsm_x4(r0, r1, r2, r3,
                        kf_inv + (uint32_t)(nip*2304 + k16*32));
                mma_f16(s[2*nip    ], qa[k16][0], qa[k16][1], qa[k16][2], qa[k16][3],
                        r0, r2);
                mma_f16(s[2*nip + 1], qa[k16][0], qa[k16][1], qa[k16][2], qa[k16][3],
                        r1, r3);
            }
        }

        // Scale + bias + online softmax (rows warp*16+g, +8)
        float nm0 = m0, nm1 = m1;
        #pragma unroll
        for (int ni = 0; ni < 8; ni++) {
            s[ni][0] = fmaf(s[ni][0], 0.125f, br0[ni].x);
            s[ni][1] = fmaf(s[ni][1], 0.125f, br0[ni].y);
            s[ni][2] = fmaf(s[ni][2], 0.125f, br1[ni].x);
            s[ni][3] = fmaf(s[ni][3], 0.125f, br1[ni].y);
            nm0 = fmaxf(nm0, fmaxf(s[ni][0], s[ni][1]));
            nm1 = fmaxf(nm1, fmaxf(s[ni][2], s[ni][3]));
        }
        nm0 = fmaxf(nm0, __shfl_xor_sync(0xffffffffu, nm0, 1));
        nm0 = fmaxf(nm0, __shfl_xor_sync(0xffffffffu, nm0, 2));
        nm1 = fmaxf(nm1, __shfl_xor_sync(0xffffffffu, nm1, 1));
        nm1 = fmaxf(nm1, __shfl_xor_sync(0xffffffffu, nm1, 2));

        float corr0 = __expf(m0 - nm0);
        float corr1 = __expf(m1 - nm1);
        float rs0 = 0.f, rs1 = 0.f;
        #pragma unroll
        for (int ni = 0; ni < 8; ni++) {
            s[ni][0] = __expf(s[ni][0] - nm0);
            s[ni][1] = __expf(s[ni][1] - nm0);
            s[ni][2] = __expf(s[ni][2] - nm1);
            s[ni][3] = __expf(s[ni][3] - nm1);
            rs0 += s[ni][0] + s[ni][1];
            rs1 += s[ni][2] + s[ni][3];
        }
        rs0 += __shfl_xor_sync(0xffffffffu, rs0, 1);
        rs0 += __shfl_xor_sync(0xffffffffu, rs0, 2);
        rs1 += __shfl_xor_sync(0xffffffffu, rs1, 1);
        rs1 += __shfl_xor_sync(0xffffffffu, rs1, 2);
        l0 = l0 * corr0 + rs0;
        l1 = l1 * corr1 + rs1;
        m0 = nm0; m1 = nm1;
        #pragma unroll
        for (int ni = 0; ni < 8; ni++) {
            o[ni][0] *= corr0; o[ni][1] *= corr0;
            o[ni][2] *= corr1; o[ni][3] *= corr1;
        }

        // GEMM2: O += P.V — P packed in-register (S-accum layout == A-frag
        // layout: a0/a1 = row g/g+8 @ k16*16+2tg (s[2k16]), a2/a3 @ +8)
        #pragma unroll
        for (int k16 = 0; k16 < 4; k16++) {
            uint32_t a0 = f2h2(s[2*k16    ][0], s[2*k16    ][1]);
            uint32_t a1 = f2h2(s[2*k16    ][2], s[2*k16    ][3]);
            uint32_t a2 = f2h2(s[2*k16 + 1][0], s[2*k16 + 1][1]);
            uint32_t a3 = f2h2(s[2*k16 + 1][2], s[2*k16 + 1][3]);
            #pragma unroll
            for (int nb = 0; nb < 4; nb++) {
                uint32_t b0, b1, b2, b3;
                ldsm_x4_trans(b0, b1, b2, b3,
                              vf_inv + (uint32_t)(k16*2304 + nb*32));
                mma_f16(o[nb*2    ], a0, a1, a2, a3, b0, b1);
                mma_f16(o[nb*2 + 1], a0, a1, a2, a3, b2, b3);
            }
        }
        // top-of-loop __syncthreads protects ks/vs for the next tile
    }

    // Normalize and write O to g_ctx [B,S,D]
    float inv0 = 1.f / l0, inv1 = 1.f / l1;
    int r0 = qt*128 + warp*16 + g;
    #pragma unroll
    for (int ni = 0; ni < 8; ni++) {
        int c = h*64 + ni*8 + tg*2;
        *(float2*)(g_ctx + (size_t)(b*NS + r0    ) * ND + c) =
            make_float2(o[ni][0]*inv0, o[ni][1]*inv0);
        *(float2*)(g_ctx + (size_t)(b*NS + r0 + 8) * ND + c) =
            make_float2(o[ni][2]*inv1, o[ni][3]*inv1);
    }
}

// ---------------------------------------------------------------------------
extern "C" void kernel_launch(void* const* d_in, const int* in_sizes, int n_in,
                              void* d_out, int out_size)
{
    const float* Q      = (const float*)d_in[0];
    const float* K      = (const float*)d_in[1];
    const float* V      = (const float*)d_in[2];
    const float* Wq     = (const float*)d_in[3];
    const float* bq     = (const float*)d_in[4];
    const float* Wk     = (const float*)d_in[5];
    const float* bk     = (const float*)d_in[6];
    const float* Wv     = (const float*)d_in[7];
    const float* bv     = (const float*)d_in[8];
    const float* Wo     = (const float*)d_in[9];
    const float* bo     = (const float*)d_in[10];
    const float* relpos = (const float*)d_in[11];
    float* out = (float*)d_out;

    // Fused QKV projections (z selects), then attention, then output proj
    dim3 gqkv(ND/128, NM/128, 3);   // (8, 64, 3)
    gemm_h<<<gqkv, 256>>>(Q, K, V, Wq, Wk, Wv, bq, bk, bv, nullptr, 0);

    dim3 gattn(NB * (NS/128), NH);  // (64, 16), batch fastest for L2 bias reuse
    attn_k<<<gattn, 256>>>(relpos);

    dim3 gout(ND/128, NM/128, 1);   // (8, 64)
    gemm_h<<<gout, 256>>>(nullptr, nullptr, nullptr, Wo, nullptr, nullptr,
                          bo, nullptr, nullptr, out, 1);
}

// round 16
// speedup vs baseline: 2.1295x; 1.1190x over previous
#include <cuda_runtime.h>
#include <cuda_fp16.h>
#include <cstdint>

// Problem constants
#define NB 4
#define NS 2048
#define ND 1024
#define NH 16
#define NDK 64
#define NM (NB*NS)   // 8192

// Persistent scratch (device globals: allocation-free, graph-safe)
__device__ __half g_xq[(size_t)NM * ND];  // converted inputs (fp16)
__device__ __half g_xk[(size_t)NM * ND];
__device__ __half g_xv[(size_t)NM * ND];
__device__ __half g_wq[(size_t)ND * ND];  // converted weights (fp16)
__device__ __half g_wk[(size_t)ND * ND];
__device__ __half g_wv[(size_t)ND * ND];
__device__ __half g_wo[(size_t)ND * ND];
__device__ __half g_q[(size_t)NM * ND];   // [B,H,S,dk] fp16
__device__ __half g_k[(size_t)NM * ND];   // [B,H,S,dk] fp16
__device__ __half g_v[(size_t)NM * ND];   // [B,H,S,dk] fp16
__device__ __half g_ctx[(size_t)NM * ND]; // [B,S,D]    fp16

// ---------------------------------------------------------------------------
// helpers
// ---------------------------------------------------------------------------
__device__ __forceinline__ uint32_t f2h2(float lo, float hi) {
    __half2 h = __floats2half2_rn(lo, hi);
    return *reinterpret_cast<uint32_t*>(&h);
}

__device__ __forceinline__ uint32_t ex2h2(uint32_t x) {
    uint32_t r;
    asm("ex2.approx.f16x2 %0, %1;" : "=r"(r) : "r"(x));
    return r;
}

__device__ __forceinline__ float2 h22f2(uint32_t p) {
    __half2 h = *reinterpret_cast<__half2*>(&p);
    return __half22float2(h);
}

__device__ __forceinline__ void mma_f16(float d[4],
                                        uint32_t a0, uint32_t a1,
                                        uint32_t a2, uint32_t a3,
                                        uint32_t b0, uint32_t b1) {
    asm volatile(
        "mma.sync.aligned.m16n8k16.row.col.f32.f16.f16.f32 "
        "{%0,%1,%2,%3}, {%4,%5,%6,%7}, {%8,%9}, {%0,%1,%2,%3};"
        : "+f"(d[0]), "+f"(d[1]), "+f"(d[2]), "+f"(d[3])
        : "r"(a0), "r"(a1), "r"(a2), "r"(a3), "r"(b0), "r"(b1));
}

__device__ __forceinline__ void ldsm_x4(uint32_t& r0, uint32_t& r1,
                                        uint32_t& r2, uint32_t& r3,
                                        uint32_t addr) {
    asm volatile(
        "ldmatrix.sync.aligned.m8n8.x4.shared.b16 {%0,%1,%2,%3}, [%4];"
        : "=r"(r0), "=r"(r1), "=r"(r2), "=r"(r3) : "r"(addr));
}

__device__ __forceinline__ void ldsm_x4_trans(uint32_t& r0, uint32_t& r1,
                                              uint32_t& r2, uint32_t& r3,
                                              uint32_t addr) {
    asm volatile(
        "ldmatrix.sync.aligned.m8n8.x4.trans.shared.b16 {%0,%1,%2,%3}, [%4];"
        : "=r"(r0), "=r"(r1), "=r"(r2), "=r"(r3) : "r"(addr));
}

__device__ __forceinline__ uint32_t smem_u32(const void* p) {
    return (uint32_t)__cvta_generic_to_shared(p);
}

// ---------------------------------------------------------------------------
// fp32 -> fp16 conversion (one-time; dst selected from device globals)
// ---------------------------------------------------------------------------
__global__ void cvt_h(const float4* __restrict__ src, int dsel, int n4)
{
    int i = blockIdx.x * blockDim.x + threadIdx.x;
    if (i >= n4) return;
    __half* dst = (dsel == 0) ? g_xq : (dsel == 1) ? g_xk : (dsel == 2) ? g_xv :
                  (dsel == 3) ? g_wq : (dsel == 4) ? g_wk : (dsel == 5) ? g_wv :
                  g_wo;
    float4 v = src[i];
    ((uint2*)dst)[i] = make_uint2(f2h2(v.x, v.y), f2h2(v.z, v.w));
}

// ---------------------------------------------------------------------------
// Projection GEMM (all-fp16 operands, m16n8k16, ldmatrix fragments).
// mode 0: fused QKV (blockIdx.z = sel 0/1/2) -> g_q/g_k/g_v
// mode 1: output projection (sel 3): X=g_ctx, W=g_wo -> Oout fp32
// 128x128 tile, BK=32 (2 k16 steps/stage), 256 threads (4m x 2n warps),
// register-prefetch double-buffered smem (pitch 40 halves: ldmatrix
// conflict-free).
// ---------------------------------------------------------------------------
__global__ __launch_bounds__(256, 2)
void gemm_h(const float* __restrict__ bq, const float* __restrict__ bk,
            const float* __restrict__ bv, const float* __restrict__ bo,
            float* __restrict__ Oout, int mode)
{
    const int sel = (mode == 0) ? (int)blockIdx.z : 3;
    const __half* X    = (sel==0) ? g_xq : (sel==1) ? g_xk : (sel==2) ? g_xv : g_ctx;
    const __half* W    = (sel==0) ? g_wq : (sel==1) ? g_wk : (sel==2) ? g_wv : g_wo;
    const float*  bias = (sel==0) ? bq   : (sel==1) ? bk   : (sel==2) ? bv   : bo;
    __half* outh = (sel==0) ? g_q : (sel==1) ? g_k : g_v;

    __shared__ __half As[2][128][40];
    __shared__ __half Bs[2][128][40];

    const int tid  = threadIdx.x;
    const int lane = tid & 31;
    const int warp = tid >> 5;
    const int g    = lane >> 2;
    const int tg   = lane & 3;
    const int mm   = lane >> 3;
    const int rr   = lane & 7;
    const int wm   = warp & 3;
    const int wn   = warp >> 2;
    const int row0 = blockIdx.y * 128;
    const int col0 = blockIdx.x * 128;

    float d[2][8][4];
    #pragma unroll
    for (int mi = 0; mi < 2; mi++)
        #pragma unroll
        for (int ni = 0; ni < 8; ni++)
            #pragma unroll
            for (int q = 0; q < 4; q++) d[mi][ni][q] = 0.f;

    // Prologue: stage 0 (128x32 halves each, uint4 = 8 halves per slot)
    #pragma unroll
    for (int w = 0; w < 2; w++) {
        int f  = tid + w * 256;        // 0..511
        int r  = f >> 2;               // 0..127
        int c8 = (f & 3) << 3;         // 0,8,16,24
        *(uint4*)&As[0][r][c8] = *(const uint4*)(X + (size_t)(row0 + r) * ND + c8);
        *(uint4*)&Bs[0][r][c8] = *(const uint4*)(W + (size_t)(col0 + r) * ND + c8);
    }
    __syncthreads();

    for (int k0 = 0; k0 < ND; k0 += 32) {
        const int buf = (k0 >> 5) & 1;
        const int nxt = buf ^ 1;
        const bool more = (k0 + 32) < ND;

        uint4 pa[2], pb[2];
        if (more) {
            #pragma unroll
            for (int w = 0; w < 2; w++) {
                int f  = tid + w * 256;
                int r  = f >> 2;
                int c8 = (f & 3) << 3;
                pa[w] = *(const uint4*)(X + (size_t)(row0 + r) * ND + k0 + 32 + c8);
                pb[w] = *(const uint4*)(W + (size_t)(col0 + r) * ND + k0 + 32 + c8);
            }
        }

        // Two k16 steps
        #pragma unroll
        for (int k16c = 0; k16c < 32; k16c += 16) {
            uint32_t af[2][4], bf[8][2];
            #pragma unroll
            for (int mi = 0; mi < 2; mi++) {
                uint32_t addr = smem_u32(
                    &As[buf][wm*32 + mi*16 + (mm&1)*8 + rr][(mm>>1)*8 + k16c]);
                ldsm_x4(af[mi][0], af[mi][1], af[mi][2], af[mi][3], addr);
            }
            #pragma unroll
            for (int nip = 0; nip < 4; nip++) {
                uint32_t addr = smem_u32(
                    &Bs[buf][wn*64 + nip*16 + (mm&1)*8 + rr][(mm>>1)*8 + k16c]);
                uint32_t r0, r1, r2, r3;
                ldsm_x4(r0, r1, r2, r3, addr);
                bf[2*nip][0] = r0; bf[2*nip+1][0] = r1;
                bf[2*nip][1] = r2; bf[2*nip+1][1] = r3;
            }
            #pragma unroll
            for (int mi = 0; mi < 2; mi++)
                #pragma unroll
                for (int ni = 0; ni < 8; ni++)
                    mma_f16(d[mi][ni], af[mi][0], af[mi][1], af[mi][2], af[mi][3],
                            bf[ni][0], bf[ni][1]);
        }

        if (more) {
            #pragma unroll
            for (int w = 0; w < 2; w++) {
                int f  = tid + w * 256;
                int r  = f >> 2;
                int c8 = (f & 3) << 3;
                *(uint4*)&As[nxt][r][c8] = pa[w];
                *(uint4*)&Bs[nxt][r][c8] = pb[w];
            }
            __syncthreads();
        }
    }

    // Epilogue: bias + write
    #pragma unroll
    for (int mi = 0; mi < 2; mi++) {
        #pragma unroll
        for (int ni = 0; ni < 8; ni++) {
            int c0 = col0 + wn * 64 + ni * 8 + tg * 2;
            float2 bb = *(const float2*)(bias + c0);
            int r0 = row0 + wm * 32 + mi * 16 + g;
            float2 v0 = make_float2(d[mi][ni][0] + bb.x, d[mi][ni][1] + bb.y);
            float2 v1 = make_float2(d[mi][ni][2] + bb.x, d[mi][ni][3] + bb.y);
            if (sel <= 2) {
                int hh = c0 >> 6, d0 = c0 & 63;
                int bt = r0 >> 11, s0 = r0 & (NS - 1);
                *(uint32_t*)(outh + (((size_t)(bt*NH + hh) * NS + s0) * NDK + d0)) =
                    f2h2(v0.x, v0.y);
                int r1 = r0 + 8;
                int bt1 = r1 >> 11, s1 = r1 & (NS - 1);
                *(uint32_t*)(outh + (((size_t)(bt1*NH + hh) * NS + s1) * NDK + d0)) =
                    f2h2(v1.x, v1.y);
            } else {
                *(float2*)(Oout + (size_t)r0 * ND + c0) = v0;
                *(float2*)(Oout + (size_t)(r0 + 8) * ND + c0) = v1;
            }
        }
    }
}

// ---------------------------------------------------------------------------
// Flash attention (fp16 m16n8k16), 256 threads / 8 warps.
// P entirely in registers; softmax exp via ex2.approx.f16x2 (2 exps/MUFU op,
// output IS the half2 P fragment). K frags ldmatrix.x4; V ldmatrix.x4.trans.
// O written to g_ctx as fp16.
// ---------------------------------------------------------------------------
__global__ __launch_bounds__(256)
void attn_k(const float* __restrict__ relpos)
{
    __shared__ __half ks16[64][72];
    __shared__ __half vs16[64][72];

    const int b    = blockIdx.x & (NB - 1);
    const int qt   = blockIdx.x >> 2;
    const int h    = blockIdx.y;
    const int tid  = threadIdx.x;
    const int lane = tid & 31;
    const int warp = tid >> 5;
    const int g    = lane >> 2;
    const int tg   = lane & 3;
    const int mm   = lane >> 3;
    const int rr   = lane & 7;

    const __half* qptr  = g_q + ((size_t)(b*NH + h) * NS + (size_t)qt*128) * NDK;
    const __half* kb16  = g_k + ((size_t)(b*NH + h) * NS) * NDK;
    const __half* vb16  = g_v + ((size_t)(b*NH + h) * NS) * NDK;
    const float*  bias0 = relpos + ((size_t)h * NS + (size_t)qt*128 + warp*16) * NS;

    // Q fragments: rows warp*16+g, +8; 4 k16 steps
    uint32_t qa[4][4];
    {
        const __half* q0 = qptr + (size_t)(warp*16 + g) * NDK;
        const __half* q1 = q0 + 8 * NDK;
        #pragma unroll
        for (int k16 = 0; k16 < 4; k16++) {
            qa[k16][0] = *(const uint32_t*)&q0[k16*16 + 2*tg];
            qa[k16][1] = *(const uint32_t*)&q1[k16*16 + 2*tg];
            qa[k16][2] = *(const uint32_t*)&q0[k16*16 + 2*tg + 8];
            qa[k16][3] = *(const uint32_t*)&q1[k16*16 + 2*tg + 8];
        }
    }

    const uint32_t kf_inv = smem_u32(&ks16[0][0])
                          + (uint32_t)(((mm & 1)*8 + rr) * 144 + (mm >> 1) * 16);
    const uint32_t vf_inv = smem_u32(&vs16[0][0])
                          + (uint32_t)(((mm & 1)*8 + rr) * 144 + (mm >> 1) * 16);

    float o[8][4];
    #pragma unroll
    for (int ni = 0; ni < 8; ni++)
        #pragma unroll
        for (int q = 0; q < 4; q++) o[ni][q] = 0.f;
    float m0 = -1e30f, m1 = -1e30f, l0 = 0.f, l1 = 0.f;
    const float L2E = 1.44269504f;

    for (int kt = 0; kt < NS/64; kt++) {
        __syncthreads();
        #pragma unroll
        for (int w = 0; w < 2; w++) {
            int f  = tid + w*256;
            int r  = f >> 3;
            int c8 = (f & 7) << 3;
            *(uint4*)&ks16[r][c8] =
                *(const uint4*)(kb16 + (size_t)(kt*64 + r)*NDK + c8);
            *(uint4*)&vs16[r][c8] =
                *(const uint4*)(vb16 + (size_t)(kt*64 + r)*NDK + c8);
        }
        __syncthreads();

        // Bias prefetch (overlaps with GEMM1)
        float2 br0[8], br1[8];
        {
            const float* bp0 = bias0 + (size_t)g * NS + kt*64 + tg*2;
            const float* bp1 = bp0 + 8 * NS;
            #pragma unroll
            for (int ni = 0; ni < 8; ni++) {
                br0[ni] = *(const float2*)(bp0 + ni*8);
                br1[ni] = *(const float2*)(bp1 + ni*8);
            }
        }

        // GEMM1: S(16x64/warp) = Q.K^T
        float s[8][4];
        #pragma unroll
        for (int ni = 0; ni < 8; ni++)
            #pragma unroll
            for (int q = 0; q < 4; q++) s[ni][q] = 0.f;

        #pragma unroll
        for (int k16 = 0; k16 < 4; k16++) {
            #pragma unroll
            for (int nip = 0; nip < 4; nip++) {
                uint32_t r0, r1, r2, r3;
                ldsm_x4(r0, r1, r2, r3,
                        kf_inv + (uint32_t)(nip*2304 + k16*32));
                mma_f16(s[2*nip    ], qa[k16][0], qa[k16][1], qa[k16][2], qa[k16][3],
                        r0, r2);
                mma_f16(s[2*nip + 1], qa[k16][0], qa[k16][1], qa[k16][2], qa[k16][3],
                        r1, r3);
            }
        }

        // Scale + bias + online softmax; P via ex2.approx.f16x2
        float nm0 = m0, nm1 = m1;
        #pragma unroll
        for (int ni = 0; ni < 8; ni++) {
            s[ni][0] = fmaf(s[ni][0], 0.125f, br0[ni].x);
            s[ni][1] = fmaf(s[ni][1], 0.125f, br0[ni].y);
            s[ni][2] = fmaf(s[ni][2], 0.125f, br1[ni].x);
            s[ni][3] = fmaf(s[ni][3], 0.125f, br1[ni].y);
            nm0 = fmaxf(nm0, fmaxf(s[ni][0], s[ni][1]));
            nm1 = fmaxf(nm1, fmaxf(s[ni][2], s[ni][3]));
        }
        nm0 = fmaxf(nm0, __shfl_xor_sync(0xffffffffu, nm0, 1));
        nm0 = fmaxf(nm0, __shfl_xor_sync(0xffffffffu, nm0, 2));
        nm1 = fmaxf(nm1, __shfl_xor_sync(0xffffffffu, nm1, 1));
        nm1 = fmaxf(nm1, __shfl_xor_sync(0xffffffffu, nm1, 2));

        float corr0 = __expf(m0 - nm0);
        float corr1 = __expf(m1 - nm1);
        const float c0s = nm0 * L2E;
        const float c1s = nm1 * L2E;
        float rs0 = 0.f, rs1 = 0.f;
        uint32_t pl[8], ph[8];
        #pragma unroll
        for (int ni = 0; ni < 8; ni++) {
            float x0 = fmaf(s[ni][0], L2E, -c0s);
            float x1 = fmaf(s[ni][1], L2E, -c0s);
            float x2 = fmaf(s[ni][2], L2E, -c1s);
            float x3 = fmaf(s[ni][3], L2E, -c1s);
            pl[ni] = ex2h2(f2h2(x0, x1));
            ph[ni] = ex2h2(f2h2(x2, x3));
            float2 p0 = h22f2(pl[ni]);
            float2 p1 = h22f2(ph[ni]);
            rs0 += p0.x + p0.y;
            rs1 += p1.x + p1.y;
        }
        rs0 += __shfl_xor_sync(0xffffffffu, rs0, 1);
        rs0 += __shfl_xor_sync(0xffffffffu, rs0, 2);
        rs1 += __shfl_xor_sync(0xffffffffu, rs1, 1);
        rs1 += __shfl_xor_sync(0xffffffffu, rs1, 2);
        l0 = l0 * corr0 + rs0;
        l1 = l1 * corr1 + rs1;
        m0 = nm0; m1 = nm1;
        #pragma unroll
        for (int ni = 0; ni < 8; ni++) {
            o[ni][0] *= corr0; o[ni][1] *= corr0;
            o[ni][2] *= corr1; o[ni][3] *= corr1;
        }

        // GEMM2: O += P.V — P fragments are the ex2 outputs directly
        #pragma unroll
        for (int k16 = 0; k16 < 4; k16++) {
            uint32_t a0 = pl[2*k16];
            uint32_t a1 = ph[2*k16];
            uint32_t a2 = pl[2*k16 + 1];
            uint32_t a3 = ph[2*k16 + 1];
            #pragma unroll
            for (int nb = 0; nb < 4; nb++) {
                uint32_t b0, b1, b2, b3;
                ldsm_x4_trans(b0, b1, b2, b3,
                              vf_inv + (uint32_t)(k16*2304 + nb*32));
                mma_f16(o[nb*2    ], a0, a1, a2, a3, b0, b1);
                mma_f16(o[nb*2 + 1], a0, a1, a2, a3, b2, b3);
            }
        }
    }

    // Normalize and write O to g_ctx [B,S,D] (fp16)
    float inv0 = 1.f / l0, inv1 = 1.f / l1;
    int r0 = qt*128 + warp*16 + g;
    #pragma unroll
    for (int ni = 0; ni < 8; ni++) {
        int c = h*64 + ni*8 + tg*2;
        *(uint32_t*)(g_ctx + (size_t)(b*NS + r0    ) * ND + c) =
            f2h2(o[ni][0]*inv0, o[ni][1]*inv0);
        *(uint32_t*)(g_ctx + (size_t)(b*NS + r0 + 8) * ND + c) =
            f2h2(o[ni][2]*inv1, o[ni][3]*inv1);
    }
}

// ---------------------------------------------------------------------------
extern "C" void kernel_launch(void* const* d_in, const int* in_sizes, int n_in,
                              void* d_out, int out_size)
{
    const float* Q      = (const float*)d_in[0];
    const float* K      = (const float*)d_in[1];
    const float* V      = (const float*)d_in[2];
    const float* Wq     = (const float*)d_in[3];
    const float* bq     = (const float*)d_in[4];
    const float* Wk     = (const float*)d_in[5];
    const float* bk     = (const float*)d_in[6];
    const float* Wv     = (const float*)d_in[7];
    const float* bv     = (const float*)d_in[8];
    const float* Wo     = (const float*)d_in[9];
    const float* bo     = (const float*)d_in[10];
    const float* relpos = (const float*)d_in[11];
    float* out = (float*)d_out;

    const int n4_in = NM * ND / 4;   // 2097152
    const int n4_w  = ND * ND / 4;   // 262144

    cvt_h<<<n4_in/256, 256>>>((const float4*)Q,  0, n4_in);
    cvt_h<<<n4_in/256, 256>>>((const float4*)K,  1, n4_in);
    cvt_h<<<n4_in/256, 256>>>((const float4*)V,  2, n4_in);
    cvt_h<<<n4_w/256,  256>>>((const float4*)Wq, 3, n4_w);
    cvt_h<<<n4_w/256,  256>>>((const float4*)Wk, 4, n4_w);
    cvt_h<<<n4_w/256,  256>>>((const float4*)Wv, 5, n4_w);
    cvt_h<<<n4_w/256,  256>>>((const float4*)Wo, 6, n4_w);

    dim3 gqkv(ND/128, NM/128, 3);   // (8, 64, 3)
    gemm_h<<<gqkv, 256>>>(bq, bk, bv, bo, nullptr, 0);

    dim3 gattn(NB * (NS/128), NH);  // (64, 16), batch fastest for L2 bias reuse
    attn_k<<<gattn, 256>>>(relpos);

    dim3 gout(ND/128, NM/128, 1);   // (8, 64)
    gemm_h<<<gout, 256>>>(bq, bk, bv, bo, out, 1);
}